// round 14
// baseline (speedup 1.0000x reference)
#include <cuda_runtime.h>
#include <cuda_fp16.h>
#include <cstdint>

#define HH 96
#define WW 96
#define NPIX (HH*WW)
#define PADW 104
#define GPIX (104*101)   // guard rows 0-1, image rows 2-97, guard rows 98-100
#define P0BASE 208       // first N-space pixel = row 2, col 0
#define NXT 78           // 9984 / 128 N tiles

// ---------------- scratch (static device globals; no allocation) ----------------
// Activations pixel-minor: buf[n][ch][GPIX]; interior (y,x) -> (y+2)*104 + x+2
__device__ __half g_xh[4*128*GPIX];     // ch 0-63: x, ch 64-127: h
__device__ float  g_c[4*64*NPIX];       // cell state (f32, [n][ch][pix])
__device__ __half g_comb[4*64*GPIX];    // fuse conv output
__device__ float  g_om[4*216*NPIX];     // offset/mask conv output (f32)
__device__ __half g_sampt[4*576*GPIX];  // DCN sampled matrix, [n][k][gpix]
__device__ __half g_fused[4*128*GPIX];  // DCN output, relu
__device__ float  g_cc[4*256*NPIX];     // gate conv output (f32)
__device__ __half g_fb[10*128*GPIX];    // cat input: ch0-63 fwd h, ch64-127 bwd h
__device__ __half g_wh[640512];         // all weights fp16 (conv weights r-major)

#define WF_FUSE 0
#define WF_OM   73728
#define WF_DCN  198144
#define WF_CC   271872
#define WF_CAT  566784

__device__ __forceinline__ float sigf(float x){ return 1.f / (1.f + __expf(-x)); }

__device__ __forceinline__ uint32_t s2u(const void* p){
    uint32_t a;
    asm("{ .reg .u64 t; cvta.to.shared.u64 t, %1; cvt.u32.u64 %0, t; }" : "=r"(a) : "l"(p));
    return a;
}
__device__ __forceinline__ void ldsm4(uint32_t r[4], uint32_t addr){
    asm volatile("ldmatrix.sync.aligned.m8n8.x4.shared.b16 {%0,%1,%2,%3}, [%4];"
        : "=r"(r[0]), "=r"(r[1]), "=r"(r[2]), "=r"(r[3]) : "r"(addr));
}
__device__ __forceinline__ void ldsm4t(uint32_t r[4], uint32_t addr){
    asm volatile("ldmatrix.sync.aligned.m8n8.x4.trans.shared.b16 {%0,%1,%2,%3}, [%4];"
        : "=r"(r[0]), "=r"(r[1]), "=r"(r[2]), "=r"(r[3]) : "r"(addr));
}
__device__ __forceinline__ void mma16(float c[4], const uint32_t a[4], uint32_t b0, uint32_t b1){
    asm volatile(
        "mma.sync.aligned.m16n8k16.row.col.f32.f16.f16.f32 "
        "{%0,%1,%2,%3}, {%4,%5,%6,%7}, {%8,%9}, {%0,%1,%2,%3};"
        : "+f"(c[0]), "+f"(c[1]), "+f"(c[2]), "+f"(c[3])
        : "r"(a[0]), "r"(a[1]), "r"(a[2]), "r"(a[3]), "r"(b0), "r"(b1));
}

static constexpr int SMEM_GEMM_TOTAL = 65536;

// ================= f16 HMMA implicit-GEMM, trans-B SMEM =================
// D[n][co][pix] = sum_k W[co][k] * Im[pix][k]  (+bias, opt relu)
// N-dimension runs over PADDED pixel space [P0BASE, P0BASE+9984); guard-column
// outputs are garbage and masked in the epilogue (guard/interior pairs homogeneous).
// A SMEM: [row=co][128B k-chunk], swizzled; normal ldmatrix (as R12).
// B SMEM: [row=k][256B = 128 px], swizzled; ldmatrix.x4.trans.
// MODE 0: conv3x3 over pixel-minor padded fp16 buffer; k = r*Cin + cin
//         (weights pre-permuted). Cin = 1<<cinlog. B k-row = pixel-contiguous.
// MODE 1: Im rows from [n][k][GPIX] dense fp16 (pixel-contiguous, aligned).
// OUTM 0: f32 flat [n][Cout][NPIX] ; 1: fp16 padded pixel-minor [n][co][GPIX]
// OUTM 2: f32 flat with n=t*2+b -> [(b*5+t)][co][NPIX]
template<int MT, int MODE, int ACT, int OUTM>
__global__ __launch_bounds__(256, 2) void tgemm(
    const __half* __restrict__ in0, long s0, int cinlog,
    const __half* __restrict__ wh, const float* __restrict__ bias,
    void* __restrict__ out, long oLane, int Cout, int K)
{
    constexpr int NB = (MT == 128) ? 4 : 2;   // B n16-tiles per warp
    extern __shared__ char dsm[];
    const uint32_t sb = s2u(dsm);
    const int tid = threadIdx.x;
    const int wid = tid >> 5;
    const int lid = tid & 31;
    const int n   = blockIdx.z;
    const int p0  = P0BASE + blockIdx.x * 128;   // padded-pixel tile base
    const int co0 = blockIdx.y * MT;

    // ---- staging roles: tid<128 stages B (k-rows x pixel), tid>=128 stages A (co rows)
    const bool isB = (tid < 128);
    const int  srow = isB ? tid : (tid - 128);
    const bool act  = isB || (srow < MT);
    const int  sco = co0 + srow;
    const bool wok = (sco < Cout) && (srow < MT);
    const uint4* wrow = (const uint4*)(wh + (long)sco * K);
    const int  sr7 = srow & 7;
    // B staging: kq = which k of the quarter, seg = which 16-px segment
    const int  kq  = tid & 15;
    const int  seg = tid >> 4;

    unsigned st[8];

    // load one quarter (16 k's): kk0 = chunk*64 + q*16
    auto ldgQ = [&](int kk0) {
        if (isB) {
            if (MODE == 0) {
                const int r    = kk0 >> cinlog;
                const int cinb = (kk0 & ((1 << cinlog) - 1)) + kq;
                const int dy   = r / 3;
                const int dx   = r - dy * 3;          // tap x = dx-1
                const __half* pb = in0 + (long)n * s0 + (long)cinb * GPIX
                                 + (p0 + seg * 16 + (dy - 1) * PADW);
                if (dx == 1) {                        // aligned
                    const uint4* qp = (const uint4*)pb;
                    uint4 a = __ldg(qp), b = __ldg(qp + 1);
                    st[0]=a.x; st[1]=a.y; st[2]=a.z; st[3]=a.w;
                    st[4]=b.x; st[5]=b.y; st[6]=b.z; st[7]=b.w;
                } else {                              // +-2B: funnel from 48B window
                    const uint4* qp = (const uint4*)(pb - ((dx == 0) ? 8 : 0));
                    uint4 a = __ldg(qp), b = __ldg(qp + 1), c = __ldg(qp + 2);
                    unsigned v[12] = {a.x,a.y,a.z,a.w, b.x,b.y,b.z,b.w, c.x,c.y,c.z,c.w};
                    const int wb = (dx == 0) ? 3 : 0;
#pragma unroll
                    for (int j = 0; j < 8; j++)
                        st[j] = __byte_perm(v[wb + j], v[wb + j + 1], 0x5432);
                }
            } else {
                const uint4* qp = (const uint4*)(in0 + (long)n * s0
                                  + (long)(kk0 + kq) * GPIX + p0 + seg * 16);
                uint4 a = __ldg(qp), b = __ldg(qp + 1);
                st[0]=a.x; st[1]=a.y; st[2]=a.z; st[3]=a.w;
                st[4]=b.x; st[5]=b.y; st[6]=b.z; st[7]=b.w;
            }
        } else if (act) {
            if (wok) {
                const uint4* wp = wrow + (kk0 >> 3);
                uint4 a = __ldg(wp), b = __ldg(wp + 1);
                st[0]=a.x; st[1]=a.y; st[2]=a.z; st[3]=a.w;
                st[4]=b.x; st[5]=b.y; st[6]=b.z; st[7]=b.w;
            } else {
#pragma unroll
                for (int j = 0; j < 8; j++) st[j] = 0u;
            }
        }
    };
    // store quarter q of buffer b
    auto stsQ = [&](int b, int q) {
        if (!act) return;
        if (isB) {
            // B region: row = k (256B), swizzle pc16 ^ (k&7)
            const int kc = q * 16 + kq;
            uint32_t base = sb + 32768u + (uint32_t)b * 16384u + (uint32_t)kc * 256u;
            const int k7 = kq & 7;
            uint32_t a0 = base + (uint32_t)(((seg * 2)     ^ k7) << 4);
            uint32_t a1 = base + (uint32_t)(((seg * 2 + 1) ^ k7) << 4);
            asm volatile("st.shared.v4.b32 [%0], {%1, %2, %3, %4};"
                :: "r"(a0), "r"(st[0]), "r"(st[1]), "r"(st[2]), "r"(st[3]) : "memory");
            asm volatile("st.shared.v4.b32 [%0], {%1, %2, %3, %4};"
                :: "r"(a1), "r"(st[4]), "r"(st[5]), "r"(st[6]), "r"(st[7]) : "memory");
        } else {
            // A region: row = co (128B), swizzle cg ^ (row&7)  (R12 layout)
            uint32_t base = sb + (uint32_t)b * 16384u + (uint32_t)srow * 128u;
#pragma unroll
            for (int c = 0; c < 2; c++) {
                int cg = 2 * q + c;
                uint32_t addr = base + (uint32_t)((cg ^ sr7) << 4);
                asm volatile("st.shared.v4.b32 [%0], {%1, %2, %3, %4};"
                    :: "r"(addr), "r"(st[4*c]), "r"(st[4*c+1]), "r"(st[4*c+2]), "r"(st[4*c+3])
                    : "memory");
            }
        }
    };

    // ---- compute-side geometry
    const int lr = lid & 7;
    const int q  = lid >> 3;
    const int wco = (MT == 128) ? (wid >> 1) * 32 : (wid >> 2) * 32;
    const int wpx = (MT == 128) ? (wid & 1) * 64  : (wid & 3) * 32;
    // A (normal ldsm, unchanged from R12)
    uint32_t offA[2]; int r7A[2]; const int kselA = q >> 1;
#pragma unroll
    for (int m = 0; m < 2; m++) {
        int r = wco + 16*m + (q & 1)*8 + lr;
        offA[m] = (uint32_t)r * 128u;  r7A[m] = r & 7;
    }
    // B (trans ldsm): per-lane k-row offset + pixel-col16 base
    const uint32_t bRow = (uint32_t)(((q & 1) * 8 + lr) * 256);
    const int pcq = (wpx >> 3) + (q >> 1);

    float acc[2][2*NB][4];
#pragma unroll
    for (int m = 0; m < 2; m++)
#pragma unroll
        for (int j = 0; j < 2*NB; j++)
#pragma unroll
            for (int v = 0; v < 4; v++) acc[m][j][v] = 0.f;

    // one k16 MMA step s (0..3) on buffer b
    auto compute_s = [&](int b, int s) {
        const uint32_t abase = sb + (uint32_t)b * 16384u;
        const uint32_t bbase = sb + 32768u + (uint32_t)b * 16384u + (uint32_t)(s * 4096) + bRow;
        uint32_t Af[2][4];
#pragma unroll
        for (int m = 0; m < 2; m++)
            ldsm4(Af[m], abase + offA[m] + (uint32_t)(((2*s + kselA) ^ r7A[m]) << 4));
#pragma unroll
        for (int j = 0; j < NB; j++) {
            uint32_t Bf[4];
            ldsm4t(Bf, bbase + (uint32_t)(((pcq + 2*j) ^ lr) << 4));
#pragma unroll
            for (int m = 0; m < 2; m++) {
                mma16(acc[m][2*j],     Af[m], Bf[0], Bf[1]);
                mma16(acc[m][2*j + 1], Af[m], Bf[2], Bf[3]);
            }
        }
    };

    // ---- pipeline: K-chunks of 64, double buffered, quarters interleaved
    const int nch = K / 64;
#pragma unroll
    for (int qq = 0; qq < 4; qq++) { ldgQ(qq * 16); stsQ(0, qq); }
    __syncthreads();
    for (int i = 0; i < nch; i++) {
        const int b = i & 1, nb = b ^ 1;
        const bool more = (i + 1 < nch);
        const int nk = (i + 1) * 64;
        if (more) ldgQ(nk);
        compute_s(b, 0);
        if (more) { stsQ(nb, 0); ldgQ(nk + 16); }
        compute_s(b, 1);
        if (more) { stsQ(nb, 1); ldgQ(nk + 32); }
        compute_s(b, 2);
        if (more) { stsQ(nb, 2); ldgQ(nk + 48); }
        compute_s(b, 3);
        if (more) stsQ(nb, 3);
        __syncthreads();
    }

    // ---- epilogue: mask guard columns; pairs are interior-homogeneous
    const int g2 = lid >> 2;
    const int tg = lid & 3;
#pragma unroll
    for (int m = 0; m < 2; m++) {
        int cobase = co0 + wco + 16 * m + g2;
#pragma unroll
        for (int half = 0; half < 2; half++) {
            int co = cobase + 8 * half;
            if (co >= Cout) continue;
            float bsv = bias[co];
#pragma unroll
            for (int j = 0; j < 2*NB; j++) {
                int pix = p0 + wpx + 2*tg + 8*j;       // padded index
                int c   = pix % PADW;
                if (c < 2 || c >= 98) continue;        // guard column pair
                float ox = acc[m][j][2*half]     + bsv;
                float oy = acc[m][j][2*half + 1] + bsv;
                if (ACT) { ox = fmaxf(ox, 0.f); oy = fmaxf(oy, 0.f); }
                if (OUTM == 1) {
                    __half* oh = (__half*)out + (long)n * oLane + (long)co * GPIX + pix;
                    *(__half2*)oh = __floats2half2_rn(ox, oy);
                } else {
                    int y  = pix / PADW - 2;
                    int up = y * WW + (c - 2);
                    long ob;
                    if (OUTM == 2) {
                        int bb = n & 1, tt = n >> 1;
                        ob = ((long)(bb * 5 + tt) * Cout + co) * NPIX + up;
                    } else {
                        ob = ((long)n * Cout + co) * NPIX + up;
                    }
                    *(float2*)((float*)out + ob) = make_float2(ox, oy);
                }
            }
        }
    }
}

// ---------------- weight convert kernels ----------------
__global__ void wperm(const float* __restrict__ w, __half* __restrict__ o, int Cin, int tot)
{
    int id = blockIdx.x * 256 + threadIdx.x;
    if (id >= tot) return;
    int r  = id % 9;
    int t2 = id / 9;
    int cin = t2 % Cin;
    int co  = t2 / Cin;
    o[(long)co * Cin * 9 + r * Cin + cin] = __float2half(w[id]);
}
__global__ void wplain(const float* __restrict__ w, __half* __restrict__ o, int tot)
{
    int id = blockIdx.x * 256 + threadIdx.x;
    if (id >= tot) return;
    o[id] = __float2half(w[id]);
}

// ---------------- stage x slices into padded pixel-minor fp16 ----------------
__global__ void stage_x(const float* __restrict__ inp, int t)
{
    int id = blockIdx.x * blockDim.x + threadIdx.x;   // 4*64*NPIX
    int p  = id % NPIX;
    int r  = id / NPIX;
    int ch = r % 64;
    int n  = r / 64;
    int b  = n & 1;
    int ts = (n < 2) ? t : (4 - t);
    int py = p / WW, px = p - py * WW;
    g_xh[((long)n * 128 + ch) * GPIX + (long)(py + 2) * PADW + px + 2] =
        __float2half(inp[(((long)b * 5 + ts) * 64 + ch) * NPIX + p]);
}

// ---------------- DCN bilinear sampler -> [n][k][GPIX] fp16 ----------------
__global__ void dcn_sample(const float* __restrict__ om, __half* __restrict__ sampt)
{
    int id = blockIdx.x * blockDim.x + threadIdx.x;   // 4*8*9*NPIX
    int p  = id % NPIX;
    int r  = id / NPIX;
    int kk = r % 9;  r /= 9;
    int g  = r % 8;
    int n  = r / 8;

    const float* omb = om + (long)n * 216 * NPIX;
    float offy = omb[((g * 9 + kk) * 2 + 0) * NPIX + p];
    float offx = omb[((g * 9 + kk) * 2 + 1) * NPIX + p];
    float m    = sigf(omb[(144 + g * 9 + kk) * NPIX + p]);

    int y  = p / WW;
    int x  = p - y * WW;
    int ky = kk / 3;
    int kx = kk - ky * 3;
    float py = (float)(y + ky - 1) + offy;
    float px = (float)(x + kx - 1) + offx;
    float fy = floorf(py), fx = floorf(px);
    float wy = py - fy,    wx = px - fx;
    int y0 = (int)fy, x0 = (int)fx;
    int y1 = y0 + 1,  x1 = x0 + 1;

    bool vy0 = (y0 >= 0) & (y0 < HH);
    bool vy1 = (y1 >= 0) & (y1 < HH);
    bool vx0 = (x0 >= 0) & (x0 < WW);
    bool vx1 = (x1 >= 0) & (x1 < WW);
    float w00 = (1.f - wy) * (1.f - wx) * (float)(vy0 && vx0);
    float w01 = (1.f - wy) * wx         * (float)(vy0 && vx1);
    float w10 = wy * (1.f - wx)         * (float)(vy1 && vx0);
    float w11 = wy * wx                 * (float)(vy1 && vx1);

    int cy0 = min(max(y0, 0), HH - 1), cy1 = min(max(y1, 0), HH - 1);
    int cx0 = min(max(x0, 0), WW - 1), cx1 = min(max(x1, 0), WW - 1);
    long i00 = (long)(cy0 + 2) * PADW + cx0 + 2, i01 = (long)(cy0 + 2) * PADW + cx1 + 2;
    long i10 = (long)(cy1 + 2) * PADW + cx0 + 2, i11 = (long)(cy1 + 2) * PADW + cx1 + 2;

    const __half* hb = g_xh + ((long)n * 128 + 64 + g * 8) * GPIX;
    __half* op = sampt + ((long)n * 576 + (long)(g * 8) * 9 + kk) * GPIX
               + (long)(y + 2) * PADW + x + 2;
#pragma unroll
    for (int cg = 0; cg < 8; cg++) {
        const __half* f = hb + (long)cg * GPIX;
        float v = w00 * __half2float(f[i00]) + w01 * __half2float(f[i01])
                + w10 * __half2float(f[i10]) + w11 * __half2float(f[i11]);
        op[(long)cg * 9 * GPIX] = __float2half(v * m);
    }
}

// ---------------- LSTM pointwise update ----------------
__global__ void lstm_k(const float* __restrict__ cc, float* __restrict__ cbuf, int t)
{
    int id = blockIdx.x * blockDim.x + threadIdx.x;   // 4*64*NPIX
    int p  = id % NPIX;
    int r  = id / NPIX;
    int ch = r % 64;
    int n  = r / 64;

    const float* c4 = cc + (long)n * 256 * NPIX;
    float ci = c4[(      ch) * NPIX + p];
    float cf = c4[( 64 + ch) * NPIX + p];
    float co = c4[(128 + ch) * NPIX + p];
    float cg = c4[(192 + ch) * NPIX + p];

    long hi = ((long)n * 64 + ch) * NPIX + p;
    float c  = cbuf[hi];
    float c2 = sigf(cf) * c + sigf(ci) * tanhf(cg);
    float h2 = sigf(co) * tanhf(c2);
    cbuf[hi] = c2;

    int py = p / WW, px = p - py * WW;
    long pidx = (long)(py + 2) * PADW + px + 2;
    __half hh = __float2half(h2);
    g_xh[((long)n * 128 + 64 + ch) * GPIX + pidx] = hh;
    if (n < 2)
        g_fb[((long)(t * 2 + n) * 128 + ch) * GPIX + pidx] = hh;
    else
        g_fb[((long)((4 - t) * 2 + (n - 2)) * 128 + 64 + ch) * GPIX + pidx] = hh;
}

// ---------------- host orchestration (graph-capturable) ----------------
extern "C" void kernel_launch(void* const* d_in, const int* in_sizes, int n_in,
                              void* d_out, int out_size)
{
    (void)in_sizes; (void)n_in; (void)out_size;
    const float* inp    = (const float*)d_in[0];
    const float* fuse_w = (const float*)d_in[1];
    const float* fuse_b = (const float*)d_in[2];
    const float* om_w   = (const float*)d_in[3];
    const float* om_b   = (const float*)d_in[4];
    const float* dcn_w  = (const float*)d_in[5];
    const float* dcn_b  = (const float*)d_in[6];
    const float* conv_w = (const float*)d_in[7];
    const float* conv_b = (const float*)d_in[8];
    const float* cat_w  = (const float*)d_in[9];
    const float* cat_b  = (const float*)d_in[10];

    __half *xh, *comb, *sampt, *fub, *fb, *wh;
    float *cb, *omb, *ccb;
    cudaGetSymbolAddress((void**)&xh,    g_xh);
    cudaGetSymbolAddress((void**)&cb,    g_c);
    cudaGetSymbolAddress((void**)&comb,  g_comb);
    cudaGetSymbolAddress((void**)&omb,   g_om);
    cudaGetSymbolAddress((void**)&sampt, g_sampt);
    cudaGetSymbolAddress((void**)&fub,   g_fused);
    cudaGetSymbolAddress((void**)&ccb,   g_cc);
    cudaGetSymbolAddress((void**)&fb,    g_fb);
    cudaGetSymbolAddress((void**)&wh,    g_wh);

    cudaFuncSetAttribute(tgemm<64,0,0,1>,  cudaFuncAttributeMaxDynamicSharedMemorySize, SMEM_GEMM_TOTAL);
    cudaFuncSetAttribute(tgemm<128,0,0,0>, cudaFuncAttributeMaxDynamicSharedMemorySize, SMEM_GEMM_TOTAL);
    cudaFuncSetAttribute(tgemm<128,1,1,1>, cudaFuncAttributeMaxDynamicSharedMemorySize, SMEM_GEMM_TOTAL);
    cudaFuncSetAttribute(tgemm<64,0,0,2>,  cudaFuncAttributeMaxDynamicSharedMemorySize, SMEM_GEMM_TOTAL);

    // weight converts (fp16, conv weights r-major permuted)
    wperm <<<288, 256>>>(fuse_w, wh + WF_FUSE, 128, 64*128*9);
    wperm <<<486, 256>>>(om_w,   wh + WF_OM,    64, 216*64*9);
    wplain<<<288, 256>>>(dcn_w,  wh + WF_DCN,       128*576);
    wperm <<<1152,256>>>(conv_w, wh + WF_CC,   128, 256*128*9);
    wperm <<<288, 256>>>(cat_w,  wh + WF_CAT,  128, 64*128*9);

    // zero padded buffers (guards must be 0) + cell state
    cudaMemsetAsync(xh,   0, sizeof(__half) * 4  * 128 * GPIX);
    cudaMemsetAsync(comb, 0, sizeof(__half) * 4  * 64  * GPIX);
    cudaMemsetAsync(fub,  0, sizeof(__half) * 4  * 128 * GPIX);
    cudaMemsetAsync(fb,   0, sizeof(__half) * 10 * 128 * GPIX);
    cudaMemsetAsync(cb,   0, sizeof(float)  * 4  * 64  * NPIX);

    for (int t = 0; t < 5; t++) {
        stage_x<<<(4*64*NPIX)/256, 256>>>(inp, t);
        // combined = conv3x3(concat(x,h)) : Cin=128, Cout=64 -> fp16 padded (M64)
        tgemm<64,0,0,1><<<dim3(NXT, 1, 4), 256, SMEM_GEMM_TOTAL>>>(
            xh, 128L*GPIX, 7, wh + WF_FUSE, fuse_b, comb, 64L*GPIX, 64, 1152);
        // om = conv3x3(combined) : Cin=64, Cout=216 -> f32 flat
        tgemm<128,0,0,0><<<dim3(NXT, 2, 4), 256, SMEM_GEMM_TOTAL>>>(
            comb, 64L*GPIX, 6, wh + WF_OM, om_b, omb, 0, 216, 576);
        // DCN sampling -> [n][576][GPIX] fp16
        dcn_sample<<<(4*8*9*NPIX)/256, 256>>>(omb, sampt);
        // fused = relu(W_dcn @ sampled) : dense K=576 -> fp16 padded
        tgemm<128,1,1,1><<<dim3(NXT, 1, 4), 256, SMEM_GEMM_TOTAL>>>(
            sampt, 576L*GPIX, 0, wh + WF_DCN, dcn_b, fub, 128L*GPIX, 128, 576);
        // cc = conv3x3(fused) : Cin=128, Cout=256 -> f32 flat
        tgemm<128,0,0,0><<<dim3(NXT, 2, 4), 256, SMEM_GEMM_TOTAL>>>(
            fub, 128L*GPIX, 7, wh + WF_CC, conv_b, ccb, 0, 256, 1152);
        // LSTM gates + state update (writes h into xh and fb)
        lstm_k<<<(4*64*NPIX)/256, 256>>>(ccb, cb, t);
    }

    // out[b][t] = conv3x3(concat(fwd,bwd)) over all 10 (t,b) lanes (M64)
    tgemm<64,0,0,2><<<dim3(NXT, 1, 10), 256, SMEM_GEMM_TOTAL>>>(
        fb, 128L*GPIX, 7, wh + WF_CAT, cat_b, d_out, 0, 64, 1152);
}

// round 15
// speedup vs baseline: 1.6681x; 1.6681x over previous
#include <cuda_runtime.h>
#include <cuda_fp16.h>
#include <cstdint>

#define HH 96
#define WW 96
#define NPIX (HH*WW)
#define PADW 100
#define PPIX 9800   // 98 rows x 100 cols, interior (y,x) -> (y+1)*100 + (x+2)

// ---------------- scratch (static device globals; no allocation) ----------------
__device__ __half g_xh[4*128*PPIX];     // ch 0-63: x, ch 64-127: h   (padded fp16)
__device__ float  g_c[4*64*NPIX];       // cell state (f32)
__device__ __half g_comb[4*64*PPIX];    // fuse conv output (padded fp16)
__device__ float  g_om[4*216*NPIX];     // offset/mask conv output (f32)
__device__ __half g_sampt[4*576*NPIX];  // DCN sampled matrix, [n][k][pix] fp16
__device__ __half g_fused[4*128*PPIX];  // DCN output, relu (padded fp16)
__device__ float  g_cc[4*256*NPIX];     // gate conv output (f32)
__device__ __half g_fb[10*128*PPIX];    // cat input: ch0-63 fwd h, ch64-127 bwd h
__device__ __half g_wh[640512];         // all weights fp16 (conv weights r-major)

// weight offsets in g_wh
#define WF_FUSE 0
#define WF_OM   73728
#define WF_DCN  198144
#define WF_CC   271872
#define WF_CAT  566784

__device__ __forceinline__ float sigf(float x){ return 1.f / (1.f + __expf(-x)); }

__device__ __forceinline__ uint32_t s2u(const void* p){
    uint32_t a;
    asm("{ .reg .u64 t; cvta.to.shared.u64 t, %1; cvt.u32.u64 %0, t; }" : "=r"(a) : "l"(p));
    return a;
}
__device__ __forceinline__ void ldsm4(uint32_t r[4], uint32_t addr){
    asm volatile("ldmatrix.sync.aligned.m8n8.x4.shared.b16 {%0,%1,%2,%3}, [%4];"
        : "=r"(r[0]), "=r"(r[1]), "=r"(r[2]), "=r"(r[3]) : "r"(addr));
}
__device__ __forceinline__ void mma16(float c[4], const uint32_t a[4], uint32_t b0, uint32_t b1){
    asm volatile(
        "mma.sync.aligned.m16n8k16.row.col.f32.f16.f16.f32 "
        "{%0,%1,%2,%3}, {%4,%5,%6,%7}, {%8,%9}, {%0,%1,%2,%3};"
        : "+f"(c[0]), "+f"(c[1]), "+f"(c[2]), "+f"(c[3])
        : "r"(a[0]), "r"(a[1]), "r"(a[2]), "r"(a[3]), "r"(b0), "r"(b1));
}

static constexpr int SMEM_GEMM_TOTAL = 65536;

// ================= f16 HMMA implicit-GEMM (R12 layouts, balanced staging) =================
// D[n][co][pix] = sum_k W[co][k] * Im[pix][k]  (+bias, opt relu)
// MT: co tile (128 or 64). Warp grid 4co x 2px (MT=128) or 2co x 4px (MT=64).
// Staging partition (NEW vs R12): thread tid stages HALF rows of both tiles:
//   brow = tid & 127 (B pixel row AND A cout row), bhalf = tid >> 7 (k-half of quarter).
//   Per quarter: 8 strided LDG.U16 (B) + 1 LDG.128 (A) + 2 STS.128.
// MODE 0: conv3x3 over padded fp16 buffer, k = r*Cin + cin (weights pre-permuted),
//         Cin = 1<<cinlog.  MODE 1: Im[pix][k] = in0[n][k][pix].
// OUTM 0: f32 flat [n][Cout][NPIX] ; 1: fp16 padded [n][co][PPIX] (oLane=ch*PPIX)
// OUTM 2: f32 flat with n=t*2+b -> [(b*5+t)][co][NPIX]
template<int MT, int MODE, int ACT, int OUTM>
__global__ __launch_bounds__(256, 2) void tgemm(
    const __half* __restrict__ in0, long s0, int cinlog,
    const __half* __restrict__ wh, const float* __restrict__ bias,
    void* __restrict__ out, long oLane, int Cout, int K)
{
    constexpr int NB = (MT == 128) ? 4 : 2;   // B n16-tiles per warp
    extern __shared__ char dsm[];
    const uint32_t sb = s2u(dsm);
    const int tid = threadIdx.x;
    const int wid = tid >> 5;
    const int lid = tid & 31;
    const int n   = blockIdx.z;
    const int p0  = blockIdx.x * 128;
    const int co0 = blockIdx.y * MT;

    // ---- balanced staging indices
    const int  brow  = tid & 127;   // B pixel row AND A cout row
    const int  bhalf = tid >> 7;    // which 8-k half of each 16-k quarter
    const int  spg = p0 + brow;
    const int  spy = spg / WW;
    const int  spx = spg - spy * WW;
    const int  sco = co0 + brow;
    const bool wok = (sco < Cout) && (brow < MT);
    const unsigned short* laneB0 =
        (const unsigned short*)(in0 + (long)n * s0) + (long)(spy + 1) * PADW + (spx + 2);
    const unsigned short* laneB1 =
        (const unsigned short*)(in0 + (long)n * s0) + spg;
    const char* wrow = (const char*)(wh + (long)sco * K);
    const int  br7 = brow & 7;

    unsigned hv[8];    // B raw u16 half-quarter
    uint4    av;       // A 16B half-quarter

    // load one half-quarter: kk0 = chunk*64 + q*16 (this thread covers k kk0+8*bhalf..+7)
    auto ldgQ = [&](int kk0) {
        const int kb = kk0 + bhalf * 8;
        if (MODE == 0) {
            const int r    = kb >> cinlog;
            const int cinb = kb & ((1 << cinlog) - 1);
            const int dy   = r / 3;
            const int pdv  = (dy - 1) * PADW + (r - dy * 3 - 1);
            const unsigned short* bt = laneB0 + (long)cinb * PPIX + pdv;
#pragma unroll
            for (int j = 0; j < 8; j++)
                hv[j] = __ldg(bt + (long)j * PPIX);
        } else {
            const unsigned short* bt = laneB1 + (long)kb * NPIX;
#pragma unroll
            for (int j = 0; j < 8; j++)
                hv[j] = __ldg(bt + (long)j * NPIX);
        }
        if (wok) av = __ldg((const uint4*)(wrow + kk0 * 2 + bhalf * 16));
        else     av = make_uint4(0u, 0u, 0u, 0u);
    };
    // store this thread's halves for quarter q of buffer b (group cg = 2q + bhalf)
    auto stsQ = [&](int b, int q) {
        unsigned st[4];
#pragma unroll
        for (int j = 0; j < 4; j++)
            st[j] = hv[2*j] | (hv[2*j + 1] << 16);
        const int cg = 2 * q + bhalf;
        const uint32_t slot = (uint32_t)((cg ^ br7) << 4);
        uint32_t addrB = sb + 32768u + (uint32_t)b * 16384u + (uint32_t)brow * 128u + slot;
        asm volatile("st.shared.v4.b32 [%0], {%1, %2, %3, %4};"
            :: "r"(addrB), "r"(st[0]), "r"(st[1]), "r"(st[2]), "r"(st[3]) : "memory");
        if (brow < MT) {
            uint32_t addrA = sb + (uint32_t)b * 16384u + (uint32_t)brow * 128u + slot;
            asm volatile("st.shared.v4.b32 [%0], {%1, %2, %3, %4};"
                :: "r"(addrA), "r"(av.x), "r"(av.y), "r"(av.z), "r"(av.w) : "memory");
        }
    };

    // ---- compute-side ldmatrix geometry (identical to R12)
    const int lr = lid & 7;
    const int q  = lid >> 3;
    const int wco = (MT == 128) ? (wid >> 1) * 32 : (wid >> 2) * 32;
    const int wpx = (MT == 128) ? (wid & 1) * 64  : (wid & 3) * 32;
    uint32_t offA[2]; int r7A[2]; const int kselA = q >> 1;
#pragma unroll
    for (int m = 0; m < 2; m++) {
        int r = wco + 16*m + (q & 1)*8 + lr;
        offA[m] = (uint32_t)r * 128u;  r7A[m] = r & 7;
    }
    uint32_t offB[NB]; int r7B[NB]; const int kselB = q & 1;
#pragma unroll
    for (int j = 0; j < NB; j++) {
        int r = wpx + 16*j + (q >> 1)*8 + lr;
        offB[j] = (uint32_t)r * 128u;  r7B[j] = r & 7;
    }

    float acc[2][2*NB][4];
#pragma unroll
    for (int m = 0; m < 2; m++)
#pragma unroll
        for (int j = 0; j < 2*NB; j++)
#pragma unroll
            for (int v = 0; v < 4; v++) acc[m][j][v] = 0.f;

    // one k16 MMA step s (0..3) on buffer b
    auto compute_s = [&](int b, int s) {
        const uint32_t abase = sb + (uint32_t)b * 16384u;
        const uint32_t bbase = sb + 32768u + (uint32_t)b * 16384u;
        uint32_t Af[2][4];
#pragma unroll
        for (int m = 0; m < 2; m++)
            ldsm4(Af[m], abase + offA[m] + (uint32_t)(((2*s + kselA) ^ r7A[m]) << 4));
#pragma unroll
        for (int j = 0; j < NB; j++) {
            uint32_t Bf[4];
            ldsm4(Bf, bbase + offB[j] + (uint32_t)(((2*s + kselB) ^ r7B[j]) << 4));
#pragma unroll
            for (int m = 0; m < 2; m++) {
                mma16(acc[m][2*j],     Af[m], Bf[0], Bf[1]);
                mma16(acc[m][2*j + 1], Af[m], Bf[2], Bf[3]);
            }
        }
    };

    // ---- pipeline: K-chunks of 64, double buffered, quarters interleaved
    const int nch = K / 64;
#pragma unroll
    for (int qq = 0; qq < 4; qq++) { ldgQ(qq * 16); stsQ(0, qq); }
    __syncthreads();
    for (int i = 0; i < nch; i++) {
        const int b = i & 1, nb = b ^ 1;
        const bool more = (i + 1 < nch);
        const int nk = (i + 1) * 64;
        if (more) ldgQ(nk);
        compute_s(b, 0);
        if (more) { stsQ(nb, 0); ldgQ(nk + 16); }
        compute_s(b, 1);
        if (more) { stsQ(nb, 1); ldgQ(nk + 32); }
        compute_s(b, 2);
        if (more) { stsQ(nb, 2); ldgQ(nk + 48); }
        compute_s(b, 3);
        if (more) stsQ(nb, 3);
        __syncthreads();
    }

    // ---- epilogue (identical to R12)
    const int g2 = lid >> 2;
    const int tg = lid & 3;
#pragma unroll
    for (int m = 0; m < 2; m++) {
        int cobase = co0 + wco + 16 * m + g2;
#pragma unroll
        for (int half = 0; half < 2; half++) {
            int co = cobase + 8 * half;
            if (co >= Cout) continue;
            float bsv = bias[co];
#pragma unroll
            for (int j = 0; j < 2*NB; j++) {
                float ox = acc[m][j][2*half]     + bsv;
                float oy = acc[m][j][2*half + 1] + bsv;
                if (ACT) { ox = fmaxf(ox, 0.f); oy = fmaxf(oy, 0.f); }
                int pix = p0 + wpx + 2*tg + 8*j;
                if (OUTM == 1) {
                    int y = pix / WW, x = pix - y * WW;
                    __half* oh = (__half*)out + (long)n * oLane + (long)co * PPIX
                               + (long)(y + 1) * PADW + (x + 2);
                    *(__half2*)oh = __floats2half2_rn(ox, oy);
                } else {
                    long ob;
                    if (OUTM == 2) {
                        int bb = n & 1, tt = n >> 1;
                        ob = ((long)(bb * 5 + tt) * Cout + co) * NPIX + pix;
                    } else {
                        ob = ((long)n * Cout + co) * NPIX + pix;
                    }
                    *(float2*)((float*)out + ob) = make_float2(ox, oy);
                }
            }
        }
    }
}

// ---------------- weight convert kernels ----------------
__global__ void wperm(const float* __restrict__ w, __half* __restrict__ o, int Cin, int tot)
{
    int id = blockIdx.x * 256 + threadIdx.x;
    if (id >= tot) return;
    int r  = id % 9;
    int t2 = id / 9;
    int cin = t2 % Cin;
    int co  = t2 / Cin;
    o[(long)co * Cin * 9 + r * Cin + cin] = __float2half(w[id]);
}
__global__ void wplain(const float* __restrict__ w, __half* __restrict__ o, int tot)
{
    int id = blockIdx.x * 256 + threadIdx.x;
    if (id >= tot) return;
    o[id] = __float2half(w[id]);
}

// ---------------- stage x slices into padded fp16 ----------------
__global__ void stage_x(const float* __restrict__ inp, int t)
{
    int id = blockIdx.x * blockDim.x + threadIdx.x;   // 4*64*NPIX
    int p  = id % NPIX;
    int r  = id / NPIX;
    int ch = r % 64;
    int n  = r / 64;
    int b  = n & 1;
    int ts = (n < 2) ? t : (4 - t);
    int py = p / WW, px = p - py * WW;
    g_xh[((long)n * 128 + ch) * PPIX + (long)(py + 1) * PADW + px + 2] =
        __float2half(inp[(((long)b * 5 + ts) * 64 + ch) * NPIX + p]);
}

// ---------------- DCN bilinear sampler -> [n][k][pix] fp16 (coalesced stores) ----------------
__global__ void dcn_sample(const float* __restrict__ om, __half* __restrict__ sampt)
{
    int id = blockIdx.x * blockDim.x + threadIdx.x;   // 4*8*9*NPIX
    int p  = id % NPIX;
    int r  = id / NPIX;
    int kk = r % 9;  r /= 9;
    int g  = r % 8;
    int n  = r / 8;

    const float* omb = om + (long)n * 216 * NPIX;
    float offy = omb[((g * 9 + kk) * 2 + 0) * NPIX + p];
    float offx = omb[((g * 9 + kk) * 2 + 1) * NPIX + p];
    float m    = sigf(omb[(144 + g * 9 + kk) * NPIX + p]);

    int y  = p / WW;
    int x  = p - y * WW;
    int ky = kk / 3;
    int kx = kk - ky * 3;
    float py = (float)(y + ky - 1) + offy;
    float px = (float)(x + kx - 1) + offx;
    float fy = floorf(py), fx = floorf(px);
    float wy = py - fy,    wx = px - fx;
    int y0 = (int)fy, x0 = (int)fx;
    int y1 = y0 + 1,  x1 = x0 + 1;

    bool vy0 = (y0 >= 0) & (y0 < HH);
    bool vy1 = (y1 >= 0) & (y1 < HH);
    bool vx0 = (x0 >= 0) & (x0 < WW);
    bool vx1 = (x1 >= 0) & (x1 < WW);
    float w00 = (1.f - wy) * (1.f - wx) * (float)(vy0 && vx0);
    float w01 = (1.f - wy) * wx         * (float)(vy0 && vx1);
    float w10 = wy * (1.f - wx)         * (float)(vy1 && vx0);
    float w11 = wy * wx                 * (float)(vy1 && vx1);

    int cy0 = min(max(y0, 0), HH - 1), cy1 = min(max(y1, 0), HH - 1);
    int cx0 = min(max(x0, 0), WW - 1), cx1 = min(max(x1, 0), WW - 1);
    long i00 = (long)(cy0 + 1) * PADW + cx0 + 2, i01 = (long)(cy0 + 1) * PADW + cx1 + 2;
    long i10 = (long)(cy1 + 1) * PADW + cx0 + 2, i11 = (long)(cy1 + 1) * PADW + cx1 + 2;

    const __half* hb = g_xh + ((long)n * 128 + 64 + g * 8) * PPIX;
    __half* op = sampt + ((long)n * 576 + (long)(g * 8) * 9 + kk) * NPIX + p;
#pragma unroll
    for (int cg = 0; cg < 8; cg++) {
        const __half* f = hb + (long)cg * PPIX;
        float v = w00 * __half2float(f[i00]) + w01 * __half2float(f[i01])
                + w10 * __half2float(f[i10]) + w11 * __half2float(f[i11]);
        op[(long)cg * 9 * NPIX] = __float2half(v * m);
    }
}

// ---------------- LSTM pointwise update ----------------
__global__ void lstm_k(const float* __restrict__ cc, float* __restrict__ cbuf, int t)
{
    int id = blockIdx.x * blockDim.x + threadIdx.x;   // 4*64*NPIX
    int p  = id % NPIX;
    int r  = id / NPIX;
    int ch = r % 64;
    int n  = r / 64;

    const float* c4 = cc + (long)n * 256 * NPIX;
    float ci = c4[(      ch) * NPIX + p];
    float cf = c4[( 64 + ch) * NPIX + p];
    float co = c4[(128 + ch) * NPIX + p];
    float cg = c4[(192 + ch) * NPIX + p];

    long hi = ((long)n * 64 + ch) * NPIX + p;
    float c  = cbuf[hi];
    float c2 = sigf(cf) * c + sigf(ci) * tanhf(cg);
    float h2 = sigf(co) * tanhf(c2);
    cbuf[hi] = c2;

    int py = p / WW, px = p - py * WW;
    long pidx = (long)(py + 1) * PADW + px + 2;
    __half hh = __float2half(h2);
    g_xh[((long)n * 128 + 64 + ch) * PPIX + pidx] = hh;
    if (n < 2)
        g_fb[((long)(t * 2 + n) * 128 + ch) * PPIX + pidx] = hh;
    else
        g_fb[((long)((4 - t) * 2 + (n - 2)) * 128 + ch) * PPIX + pidx + 64 * PPIX] = hh;
}

// ---------------- host orchestration (graph-capturable) ----------------
extern "C" void kernel_launch(void* const* d_in, const int* in_sizes, int n_in,
                              void* d_out, int out_size)
{
    (void)in_sizes; (void)n_in; (void)out_size;
    const float* inp    = (const float*)d_in[0];
    const float* fuse_w = (const float*)d_in[1];
    const float* fuse_b = (const float*)d_in[2];
    const float* om_w   = (const float*)d_in[3];
    const float* om_b   = (const float*)d_in[4];
    const float* dcn_w  = (const float*)d_in[5];
    const float* dcn_b  = (const float*)d_in[6];
    const float* conv_w = (const float*)d_in[7];
    const float* conv_b = (const float*)d_in[8];
    const float* cat_w  = (const float*)d_in[9];
    const float* cat_b  = (const float*)d_in[10];

    __half *xh, *comb, *sampt, *fub, *fb, *wh;
    float *cb, *omb, *ccb;
    cudaGetSymbolAddress((void**)&xh,    g_xh);
    cudaGetSymbolAddress((void**)&cb,    g_c);
    cudaGetSymbolAddress((void**)&comb,  g_comb);
    cudaGetSymbolAddress((void**)&omb,   g_om);
    cudaGetSymbolAddress((void**)&sampt, g_sampt);
    cudaGetSymbolAddress((void**)&fub,   g_fused);
    cudaGetSymbolAddress((void**)&ccb,   g_cc);
    cudaGetSymbolAddress((void**)&fb,    g_fb);
    cudaGetSymbolAddress((void**)&wh,    g_wh);

    cudaFuncSetAttribute(tgemm<64,0,0,1>,  cudaFuncAttributeMaxDynamicSharedMemorySize, SMEM_GEMM_TOTAL);
    cudaFuncSetAttribute(tgemm<128,0,0,0>, cudaFuncAttributeMaxDynamicSharedMemorySize, SMEM_GEMM_TOTAL);
    cudaFuncSetAttribute(tgemm<128,1,1,1>, cudaFuncAttributeMaxDynamicSharedMemorySize, SMEM_GEMM_TOTAL);
    cudaFuncSetAttribute(tgemm<64,0,0,2>,  cudaFuncAttributeMaxDynamicSharedMemorySize, SMEM_GEMM_TOTAL);

    // weight converts (fp16, conv weights r-major permuted)
    wperm <<<288, 256>>>(fuse_w, wh + WF_FUSE, 128, 64*128*9);
    wperm <<<486, 256>>>(om_w,   wh + WF_OM,    64, 216*64*9);
    wplain<<<288, 256>>>(dcn_w,  wh + WF_DCN,       128*576);
    wperm <<<1152,256>>>(conv_w, wh + WF_CC,   128, 256*128*9);
    wperm <<<288, 256>>>(cat_w,  wh + WF_CAT,  128, 64*128*9);

    // zero padded buffers (borders must be 0) + cell state
    cudaMemsetAsync(xh,   0, sizeof(__half) * 4  * 128 * PPIX);
    cudaMemsetAsync(comb, 0, sizeof(__half) * 4  * 64  * PPIX);
    cudaMemsetAsync(fub,  0, sizeof(__half) * 4  * 128 * PPIX);
    cudaMemsetAsync(fb,   0, sizeof(__half) * 10 * 128 * PPIX);
    cudaMemsetAsync(cb,   0, sizeof(float)  * 4  * 64  * NPIX);

    for (int t = 0; t < 5; t++) {
        stage_x<<<(4*64*NPIX)/256, 256>>>(inp, t);
        // combined = conv3x3(concat(x,h)) : Cin=128, Cout=64 -> fp16 padded (M64)
        tgemm<64,0,0,1><<<dim3(72, 1, 4), 256, SMEM_GEMM_TOTAL>>>(
            xh, 128L*PPIX, 7, wh + WF_FUSE, fuse_b, comb, 64L*PPIX, 64, 1152);
        // om = conv3x3(combined) : Cin=64, Cout=216 -> f32 flat
        tgemm<128,0,0,0><<<dim3(72, 2, 4), 256, SMEM_GEMM_TOTAL>>>(
            comb, 64L*PPIX, 6, wh + WF_OM, om_b, omb, 0, 216, 576);
        // DCN sampling -> [n][576][NPIX] fp16
        dcn_sample<<<(4*8*9*NPIX)/256, 256>>>(omb, sampt);
        // fused = relu(W_dcn @ sampled) : dense K=576 -> fp16 padded
        tgemm<128,1,1,1><<<dim3(72, 1, 4), 256, SMEM_GEMM_TOTAL>>>(
            sampt, 576L*NPIX, 0, wh + WF_DCN, dcn_b, fub, 128L*PPIX, 128, 576);
        // cc = conv3x3(fused) : Cin=128, Cout=256 -> f32 flat
        tgemm<128,0,0,0><<<dim3(72, 2, 4), 256, SMEM_GEMM_TOTAL>>>(
            fub, 128L*PPIX, 7, wh + WF_CC, conv_b, ccb, 0, 256, 1152);
        // LSTM gates + state update (writes h into xh and fb)
        lstm_k<<<(4*64*NPIX)/256, 256>>>(ccb, cb, t);
    }

    // out[b][t] = conv3x3(concat(fwd,bwd)) over all 10 (t,b) lanes (M64)
    tgemm<64,0,0,2><<<dim3(72, 1, 10), 256, SMEM_GEMM_TOTAL>>>(
        fb, 128L*PPIX, 7, wh + WF_CAT, cat_b, d_out, 0, 64, 1152);
}

// round 17
// speedup vs baseline: 1.6854x; 1.0103x over previous
#include <cuda_runtime.h>
#include <cuda_fp16.h>
#include <cstdint>

#define HH 96
#define WW 96
#define NPIX (HH*WW)
#define PADW 100
#define PPIX 9800   // 98 rows x 100 cols, interior (y,x) -> (y+1)*100 + (x+2)

// ---------------- scratch (static device globals; no allocation) ----------------
__device__ __half g_xall[10*64*PPIX];   // x slices for all (b,ts), padded fp16
__device__ __half g_xh[4*128*PPIX];     // ch 64-127: h state (padded fp16); ch 0-63 unused
__device__ float  g_c[4*64*NPIX];       // cell state (f32)
__device__ __half g_comb[4*64*PPIX];    // fuse conv output (padded fp16)
__device__ __half g_om[4*216*NPIX];     // offset/mask conv output (fp16 flat)
__device__ __half g_sampt[4*576*NPIX];  // DCN sampled matrix, [n][k][pix] fp16
__device__ __half g_fused[4*128*PPIX];  // DCN output, relu (padded fp16)
__device__ __half g_fb[10*128*PPIX];    // cat input: ch0-63 fwd h, ch64-127 bwd h
__device__ __half g_wh[640512];         // all weights fp16 (conv weights r-major)

// weight offsets in g_wh
#define WF_FUSE 0
#define WF_OM   73728
#define WF_DCN  198144
#define WF_CC   271872
#define WF_CAT  566784

__device__ __forceinline__ float sigf(float x){ return 1.f / (1.f + __expf(-x)); }
__device__ __forceinline__ float tanha(float x){
    float r; asm("tanh.approx.f32 %0, %1;" : "=f"(r) : "f"(x)); return r;
}
__device__ __forceinline__ float siga(float x){ return 0.5f * tanha(0.5f * x) + 0.5f; }

__device__ __forceinline__ uint32_t s2u(const void* p){
    uint32_t a;
    asm("{ .reg .u64 t; cvta.to.shared.u64 t, %1; cvt.u32.u64 %0, t; }" : "=r"(a) : "l"(p));
    return a;
}
__device__ __forceinline__ void ldsm4(uint32_t r[4], uint32_t addr){
    asm volatile("ldmatrix.sync.aligned.m8n8.x4.shared.b16 {%0,%1,%2,%3}, [%4];"
        : "=r"(r[0]), "=r"(r[1]), "=r"(r[2]), "=r"(r[3]) : "r"(addr));
}
__device__ __forceinline__ void mma16(float c[4], const uint32_t a[4], uint32_t b0, uint32_t b1){
    asm volatile(
        "mma.sync.aligned.m16n8k16.row.col.f32.f16.f16.f32 "
        "{%0,%1,%2,%3}, {%4,%5,%6,%7}, {%8,%9}, {%0,%1,%2,%3};"
        : "+f"(c[0]), "+f"(c[1]), "+f"(c[2]), "+f"(c[3])
        : "r"(a[0]), "r"(a[1]), "r"(a[2]), "r"(a[3]), "r"(b0), "r"(b1));
}

static constexpr int SMEM_GEMM_TOTAL = 65536;
static constexpr int SMEM_LSTM_TOTAL = 128 * 129 * 4;   // 66048 (cc+lstm template)

// ================= f16 HMMA implicit-GEMM (R15 mainloop) =================
// D[n][co][pix] = sum_k W[co][k] * Im[pix][k]  (+bias per OUTM)
// MT: co tile. Warp grid 4co x 2px (MT=128) or 2co x 4px (MT=64).
// Balanced staging: thread stages half-rows of BOTH tiles (brow = tid&127,
// bhalf = tid>>7): per quarter 8 strided LDG.U16 (B) + 1 LDG.128 (A) + 2 STS.128.
// MODE 0: conv3x3 over padded fp16 buffer in0, k = r*Cin + cin, Cin=1<<cinlog.
// MODE 1: Im[pix][k] = in0[n][k][pix].
// MODE 2: conv3x3 over concat(x-slice(t,n) from g_xall, h from g_xh), Cin=128.
// OUTM 1: fp16 padded [n][co][PPIX] (+bias, opt ACT relu)
// OUTM 2: f32 flat, n=t*2+b -> [(b*5+t)][co][NPIX] (+bias)
// OUTM 3: fp16 flat [n][co][NPIX] (+bias)
// OUTM 4: fused LSTM epilogue (gate-interleaved weights; bias applied here;
//         writes h -> g_xh & g_fb, c -> g_c; 'out' unused)
template<int MT, int MODE, int ACT, int OUTM>
__global__ __launch_bounds__(256, 2) void tgemm(
    const __half* __restrict__ in0, long s0, int cinlog,
    const __half* __restrict__ wh, const float* __restrict__ bias,
    void* __restrict__ out, long oLane, int Cout, int K, int tpar)
{
    constexpr int NB = (MT == 128) ? 4 : 2;
    extern __shared__ char dsm[];
    const uint32_t sb = s2u(dsm);
    const int tid = threadIdx.x;
    const int wid = tid >> 5;
    const int lid = tid & 31;
    const int n   = blockIdx.z;
    const int p0  = blockIdx.x * 128;
    const int co0 = blockIdx.y * MT;

    // ---- balanced staging indices
    const int  brow  = tid & 127;
    const int  bhalf = tid >> 7;
    const int  spg = p0 + brow;
    const int  spy = spg / WW;
    const int  spx = spg - spy * WW;
    const int  sco = co0 + brow;
    const bool wok = (sco < Cout) && (brow < MT);
    const long pixoff = (long)(spy + 1) * PADW + (spx + 2);
    const unsigned short* laneB0 = (MODE == 0)
        ? (const unsigned short*)(in0 + (long)n * s0) + pixoff : (const unsigned short*)0;
    const unsigned short* laneB1 = (MODE == 1)
        ? (const unsigned short*)(in0 + (long)n * s0) + spg : (const unsigned short*)0;
    const unsigned short* laneBx = (const unsigned short*)0;
    const unsigned short* laneBh = (const unsigned short*)0;
    if (MODE == 2) {
        const int ts = (n < 2) ? tpar : (4 - tpar);
        const int sl = (n & 1) * 5 + ts;
        laneBx = (const unsigned short*)g_xall + (long)sl * 64 * PPIX + pixoff;
        laneBh = (const unsigned short*)g_xh + ((long)n * 128 + 64) * PPIX + pixoff;
    }
    const char* wrow = (const char*)(wh + (long)sco * K);
    const int  br7 = brow & 7;

    unsigned hv[8];
    uint4    av;

    auto ldgQ = [&](int kk0) {
        const int kb = kk0 + bhalf * 8;
        if (MODE == 0) {
            const int r    = kb >> cinlog;
            const int cinb = kb & ((1 << cinlog) - 1);
            const int dy   = r / 3;
            const int pdv  = (dy - 1) * PADW + (r - dy * 3 - 1);
            const unsigned short* bt = laneB0 + (long)cinb * PPIX + pdv;
#pragma unroll
            for (int j = 0; j < 8; j++)
                hv[j] = __ldg(bt + (long)j * PPIX);
        } else if (MODE == 1) {
            const unsigned short* bt = laneB1 + (long)kb * NPIX;
#pragma unroll
            for (int j = 0; j < 8; j++)
                hv[j] = __ldg(bt + (long)j * NPIX);
        } else {
            const int r    = kb >> 7;
            const int cinb = kb & 127;
            const int dy   = r / 3;
            const int pdv  = (dy - 1) * PADW + (r - dy * 3 - 1);
            const unsigned short* bt = (cinb < 64)
                ? (laneBx + (long)cinb * PPIX + pdv)
                : (laneBh + (long)(cinb - 64) * PPIX + pdv);
#pragma unroll
            for (int j = 0; j < 8; j++)
                hv[j] = __ldg(bt + (long)j * PPIX);
        }
        if (wok) av = __ldg((const uint4*)(wrow + kk0 * 2 + bhalf * 16));
        else     av = make_uint4(0u, 0u, 0u, 0u);
    };
    auto stsQ = [&](int b, int q) {
        unsigned st[4];
#pragma unroll
        for (int j = 0; j < 4; j++)
            st[j] = hv[2*j] | (hv[2*j + 1] << 16);
        const int cg = 2 * q + bhalf;
        const uint32_t slot = (uint32_t)((cg ^ br7) << 4);
        uint32_t addrB = sb + 32768u + (uint32_t)b * 16384u + (uint32_t)brow * 128u + slot;
        asm volatile("st.shared.v4.b32 [%0], {%1, %2, %3, %4};"
            :: "r"(addrB), "r"(st[0]), "r"(st[1]), "r"(st[2]), "r"(st[3]) : "memory");
        if (brow < MT) {
            uint32_t addrA = sb + (uint32_t)b * 16384u + (uint32_t)brow * 128u + slot;
            asm volatile("st.shared.v4.b32 [%0], {%1, %2, %3, %4};"
                :: "r"(addrA), "r"(av.x), "r"(av.y), "r"(av.z), "r"(av.w) : "memory");
        }
    };

    // ---- compute-side ldmatrix geometry
    const int lr = lid & 7;
    const int q  = lid >> 3;
    const int wco = (MT == 128) ? (wid >> 1) * 32 : (wid >> 2) * 32;
    const int wpx = (MT == 128) ? (wid & 1) * 64  : (wid & 3) * 32;
    uint32_t offA[2]; int r7A[2]; const int kselA = q >> 1;
#pragma unroll
    for (int m = 0; m < 2; m++) {
        int r = wco + 16*m + (q & 1)*8 + lr;
        offA[m] = (uint32_t)r * 128u;  r7A[m] = r & 7;
    }
    uint32_t offB[NB]; int r7B[NB]; const int kselB = q & 1;
#pragma unroll
    for (int j = 0; j < NB; j++) {
        int r = wpx + 16*j + (q >> 1)*8 + lr;
        offB[j] = (uint32_t)r * 128u;  r7B[j] = r & 7;
    }

    float acc[2][2*NB][4];
#pragma unroll
    for (int m = 0; m < 2; m++)
#pragma unroll
        for (int j = 0; j < 2*NB; j++)
#pragma unroll
            for (int v = 0; v < 4; v++) acc[m][j][v] = 0.f;

    auto compute_s = [&](int b, int s) {
        const uint32_t abase = sb + (uint32_t)b * 16384u;
        const uint32_t bbase = sb + 32768u + (uint32_t)b * 16384u;
        uint32_t Af[2][4];
#pragma unroll
        for (int m = 0; m < 2; m++)
            ldsm4(Af[m], abase + offA[m] + (uint32_t)(((2*s + kselA) ^ r7A[m]) << 4));
#pragma unroll
        for (int j = 0; j < NB; j++) {
            uint32_t Bf[4];
            ldsm4(Bf, bbase + offB[j] + (uint32_t)(((2*s + kselB) ^ r7B[j]) << 4));
#pragma unroll
            for (int m = 0; m < 2; m++) {
                mma16(acc[m][2*j],     Af[m], Bf[0], Bf[1]);
                mma16(acc[m][2*j + 1], Af[m], Bf[2], Bf[3]);
            }
        }
    };

    // ---- pipeline: K-chunks of 64, double buffered, quarters interleaved
    const int nch = K / 64;
#pragma unroll
    for (int qq = 0; qq < 4; qq++) { ldgQ(qq * 16); stsQ(0, qq); }
    __syncthreads();
    for (int i = 0; i < nch; i++) {
        const int b = i & 1, nb = b ^ 1;
        const bool more = (i + 1 < nch);
        const int nk = (i + 1) * 64;
        if (more) ldgQ(nk);
        compute_s(b, 0);
        if (more) { stsQ(nb, 0); ldgQ(nk + 16); }
        compute_s(b, 1);
        if (more) { stsQ(nb, 1); ldgQ(nk + 32); }
        compute_s(b, 2);
        if (more) { stsQ(nb, 2); ldgQ(nk + 48); }
        compute_s(b, 3);
        if (more) stsQ(nb, 3);
        __syncthreads();
    }

    // ---- epilogue
    const int g2 = lid >> 2;
    const int tg = lid & 3;
    if (OUTM != 4) {
#pragma unroll
        for (int m = 0; m < 2; m++) {
            int cobase = co0 + wco + 16 * m + g2;
#pragma unroll
            for (int half = 0; half < 2; half++) {
                int co = cobase + 8 * half;
                if (co >= Cout) continue;
                float bsv = bias[co];
#pragma unroll
                for (int j = 0; j < 2*NB; j++) {
                    float ox = acc[m][j][2*half]     + bsv;
                    float oy = acc[m][j][2*half + 1] + bsv;
                    if (ACT) { ox = fmaxf(ox, 0.f); oy = fmaxf(oy, 0.f); }
                    int pix = p0 + wpx + 2*tg + 8*j;
                    if (OUTM == 1) {
                        int y = pix / WW, x = pix - y * WW;
                        __half* oh = (__half*)out + (long)n * oLane + (long)co * PPIX
                                   + (long)(y + 1) * PADW + (x + 2);
                        *(__half2*)oh = __floats2half2_rn(ox, oy);
                    } else if (OUTM == 3) {
                        __half* oh = (__half*)out + ((long)n * Cout + co) * NPIX + pix;
                        *(__half2*)oh = __floats2half2_rn(ox, oy);
                    } else {
                        long ob;
                        if (OUTM == 2) {
                            int bb = n & 1, tt = n >> 1;
                            ob = ((long)(bb * 5 + tt) * Cout + co) * NPIX + pix;
                        } else {
                            ob = ((long)n * Cout + co) * NPIX + pix;
                        }
                        *(float2*)((float*)out + ob) = make_float2(ox, oy);
                    }
                }
            }
        }
    } else {
        // -------- fused LSTM epilogue (MT=128). Tile rows = gate*32 + ch_l,
        // channels 32*blockIdx.y + ch_l. Exchange acc via SMEM [px][row], stride 129.
        float* sacc = (float*)dsm;
#pragma unroll
        for (int m = 0; m < 2; m++)
#pragma unroll
            for (int half = 0; half < 2; half++) {
                int row = wco + 16 * m + g2 + 8 * half;
#pragma unroll
                for (int j = 0; j < 2*NB; j++) {
                    int pxr = wpx + 2*tg + 8*j;
                    sacc[pxr * 129 + row]       = acc[m][j][2*half];
                    sacc[(pxr + 1) * 129 + row] = acc[m][j][2*half + 1];
                }
            }
        __syncthreads();
#pragma unroll
        for (int e = 0; e < 16; e++) {
            int flat = e * 256 + tid;
            int px   = flat & 127;
            int chl  = flat >> 7;
            int ch   = (int)blockIdx.y * 32 + chl;
            float iv = sacc[px * 129 +      chl] + __ldg(bias + ch);
            float fv = sacc[px * 129 + 32 + chl] + __ldg(bias + 64 + ch);
            float ov = sacc[px * 129 + 64 + chl] + __ldg(bias + 128 + ch);
            float gv = sacc[px * 129 + 96 + chl] + __ldg(bias + 192 + ch);
            long cidx = ((long)n * 64 + ch) * NPIX + p0 + px;
            float c  = g_c[cidx];
            float c2 = siga(fv) * c + siga(iv) * tanha(gv);
            float h2 = siga(ov) * tanha(c2);
            g_c[cidx] = c2;
            int pg = p0 + px;
            int py = pg / WW, pxx = pg - py * WW;
            long pidx = (long)(py + 1) * PADW + pxx + 2;
            __half hh = __float2half(h2);
            g_xh[((long)n * 128 + 64 + ch) * PPIX + pidx] = hh;
            int t2b = (n < 2) ? (tpar * 2 + n) : ((4 - tpar) * 2 + (n - 2));
            g_fb[((long)t2b * 128 + ((n < 2) ? 0 : 64) + ch) * PPIX + pidx] = hh;
        }
    }
}

// ---------------- weight convert kernels ----------------
__global__ void wperm(const float* __restrict__ w, __half* __restrict__ o, int Cin, int tot)
{
    int id = blockIdx.x * 256 + threadIdx.x;
    if (id >= tot) return;
    int r  = id % 9;
    int t2 = id / 9;
    int cin = t2 % Cin;
    int co  = t2 / Cin;
    o[(long)co * Cin * 9 + r * Cin + cin] = __float2half(w[id]);
}
// cc weights: r-major k AND gate-interleaved rows: co=(g*64+c) -> (c>>5)*128 + g*32 + (c&31)
__global__ void wpermg(const float* __restrict__ w, __half* __restrict__ o, int tot)
{
    int id = blockIdx.x * 256 + threadIdx.x;
    if (id >= tot) return;
    int r  = id % 9;
    int t2 = id / 9;
    int cin = t2 % 128;
    int co  = t2 / 128;
    int g_ = co >> 6, c = co & 63;
    int rp = (c >> 5) * 128 + g_ * 32 + (c & 31);
    o[(long)rp * 1152 + r * 128 + cin] = __float2half(w[id]);
}
__global__ void wplain(const float* __restrict__ w, __half* __restrict__ o, int tot)
{
    int id = blockIdx.x * 256 + threadIdx.x;
    if (id >= tot) return;
    o[id] = __float2half(w[id]);
}

// ---------------- stage ALL x slices into padded fp16 (once) ----------------
__global__ void stage_x_all(const float* __restrict__ inp)
{
    int id = blockIdx.x * blockDim.x + threadIdx.x;   // 10*64*NPIX
    int p  = id % NPIX;
    int r  = id / NPIX;      // slice*64 + ch, slice = b*5+ts matches input order
    int py = p / WW, px = p - py * WW;
    g_xall[(long)r * PPIX + (long)(py + 1) * PADW + px + 2] =
        __float2half(inp[(long)r * NPIX + p]);
}

// ---------------- DCN bilinear sampler (om fp16) -> [n][k][pix] fp16 ----------------
__global__ void dcn_sample(const __half* __restrict__ om, __half* __restrict__ sampt)
{
    int id = blockIdx.x * blockDim.x + threadIdx.x;   // 4*8*9*NPIX
    int p  = id % NPIX;
    int r  = id / NPIX;
    int kk = r % 9;  r /= 9;
    int g  = r % 8;
    int n  = r / 8;

    const __half* omb = om + (long)n * 216 * NPIX;
    float offy = __half2float(omb[((g * 9 + kk) * 2 + 0) * NPIX + p]);
    float offx = __half2float(omb[((g * 9 + kk) * 2 + 1) * NPIX + p]);
    float m    = sigf(__half2float(omb[(144 + g * 9 + kk) * NPIX + p]));

    int y  = p / WW;
    int x  = p - y * WW;
    int ky = kk / 3;
    int kx = kk - ky * 3;
    float py = (float)(y + ky - 1) + offy;
    float px = (float)(x + kx - 1) + offx;
    float fy = floorf(py), fx = floorf(px);
    float wy = py - fy,    wx = px - fx;
    int y0 = (int)fy, x0 = (int)fx;
    int y1 = y0 + 1,  x1 = x0 + 1;

    bool vy0 = (y0 >= 0) & (y0 < HH);
    bool vy1 = (y1 >= 0) & (y1 < HH);
    bool vx0 = (x0 >= 0) & (x0 < WW);
    bool vx1 = (x1 >= 0) & (x1 < WW);
    float w00 = (1.f - wy) * (1.f - wx) * (float)(vy0 && vx0);
    float w01 = (1.f - wy) * wx         * (float)(vy0 && vx1);
    float w10 = wy * (1.f - wx)         * (float)(vy1 && vx0);
    float w11 = wy * wx                 * (float)(vy1 && vx1);

    int cy0 = min(max(y0, 0), HH - 1), cy1 = min(max(y1, 0), HH - 1);
    int cx0 = min(max(x0, 0), WW - 1), cx1 = min(max(x1, 0), WW - 1);
    long i00 = (long)(cy0 + 1) * PADW + cx0 + 2, i01 = (long)(cy0 + 1) * PADW + cx1 + 2;
    long i10 = (long)(cy1 + 1) * PADW + cx0 + 2, i11 = (long)(cy1 + 1) * PADW + cx1 + 2;

    const __half* hb = g_xh + ((long)n * 128 + 64 + g * 8) * PPIX;
    __half* op = sampt + ((long)n * 576 + (long)(g * 8) * 9 + kk) * NPIX + p;
#pragma unroll
    for (int cg = 0; cg < 8; cg++) {
        const __half* f = hb + (long)cg * PPIX;
        float v = w00 * __half2float(f[i00]) + w01 * __half2float(f[i01])
                + w10 * __half2float(f[i10]) + w11 * __half2float(f[i11]);
        op[(long)cg * 9 * NPIX] = __float2half(v * m);
    }
}

// ---------------- host orchestration (graph-capturable) ----------------
extern "C" void kernel_launch(void* const* d_in, const int* in_sizes, int n_in,
                              void* d_out, int out_size)
{
    (void)in_sizes; (void)n_in; (void)out_size;
    const float* inp    = (const float*)d_in[0];
    const float* fuse_w = (const float*)d_in[1];
    const float* fuse_b = (const float*)d_in[2];
    const float* om_w   = (const float*)d_in[3];
    const float* om_b   = (const float*)d_in[4];
    const float* dcn_w  = (const float*)d_in[5];
    const float* dcn_b  = (const float*)d_in[6];
    const float* conv_w = (const float*)d_in[7];
    const float* conv_b = (const float*)d_in[8];
    const float* cat_w  = (const float*)d_in[9];
    const float* cat_b  = (const float*)d_in[10];

    __half *xall, *xh, *comb, *omb, *sampt, *fub, *fb, *wh;
    float *cb;
    cudaGetSymbolAddress((void**)&xall,  g_xall);
    cudaGetSymbolAddress((void**)&xh,    g_xh);
    cudaGetSymbolAddress((void**)&cb,    g_c);
    cudaGetSymbolAddress((void**)&comb,  g_comb);
    cudaGetSymbolAddress((void**)&omb,   g_om);
    cudaGetSymbolAddress((void**)&sampt, g_sampt);
    cudaGetSymbolAddress((void**)&fub,   g_fused);
    cudaGetSymbolAddress((void**)&fb,    g_fb);
    cudaGetSymbolAddress((void**)&wh,    g_wh);

    cudaFuncSetAttribute(tgemm<64,2,0,1>,  cudaFuncAttributeMaxDynamicSharedMemorySize, SMEM_GEMM_TOTAL);
    cudaFuncSetAttribute(tgemm<128,0,0,3>, cudaFuncAttributeMaxDynamicSharedMemorySize, SMEM_GEMM_TOTAL);
    cudaFuncSetAttribute(tgemm<128,1,1,1>, cudaFuncAttributeMaxDynamicSharedMemorySize, SMEM_GEMM_TOTAL);
    cudaFuncSetAttribute(tgemm<128,0,0,4>, cudaFuncAttributeMaxDynamicSharedMemorySize, SMEM_LSTM_TOTAL);
    cudaFuncSetAttribute(tgemm<64,0,0,2>,  cudaFuncAttributeMaxDynamicSharedMemorySize, SMEM_GEMM_TOTAL);

    // ---- prologue ordered so launch #6 is a tgemm (for ncu -s 5 -c 1) ----
    wperm<<<288, 256>>>(fuse_w, wh + WF_FUSE, 128, 64*128*9);                 // 1
    cudaMemsetAsync(xall, 0, sizeof(__half) * 10 * 64  * PPIX);              // 2
    cudaMemsetAsync(xh,   0, sizeof(__half) * 4  * 128 * PPIX);              // 3
    cudaMemsetAsync(comb, 0, sizeof(__half) * 4  * 64  * PPIX);              // 4
    stage_x_all<<<(10*64*NPIX)/256, 256>>>(inp);                             // 5
    // t=0 fuse conv (h=0): combined = conv3x3(concat(x,h))                  // 6 <- profiled
    tgemm<64,2,0,1><<<dim3(72, 1, 4), 256, SMEM_GEMM_TOTAL>>>(
        (const __half*)0, 0, 7, wh + WF_FUSE, fuse_b, comb, 64L*PPIX, 64, 1152, 0);

    // remaining converts / clears (before their first consumers)
    wperm <<<486, 256>>>(om_w,   wh + WF_OM,    64, 216*64*9);
    wplain<<<288, 256>>>(dcn_w,  wh + WF_DCN,       128*576);
    wpermg<<<1152,256>>>(conv_w, wh + WF_CC,        256*128*9);
    wperm <<<288, 256>>>(cat_w,  wh + WF_CAT,  128, 64*128*9);
    cudaMemsetAsync(fub, 0, sizeof(__half) * 4  * 128 * PPIX);
    cudaMemsetAsync(fb,  0, sizeof(__half) * 10 * 128 * PPIX);
    cudaMemsetAsync(cb,  0, sizeof(float)  * 4  * 64  * NPIX);

    for (int t = 0; t < 5; t++) {
        if (t > 0) {
            // combined = conv3x3(concat(x_t, h)) : Cin=128, Cout=64 (M64)
            tgemm<64,2,0,1><<<dim3(72, 1, 4), 256, SMEM_GEMM_TOTAL>>>(
                (const __half*)0, 0, 7, wh + WF_FUSE, fuse_b, comb, 64L*PPIX, 64, 1152, t);
        }
        // om = conv3x3(combined) : Cin=64, Cout=216 -> fp16 flat
        tgemm<128,0,0,3><<<dim3(72, 2, 4), 256, SMEM_GEMM_TOTAL>>>(
            comb, 64L*PPIX, 6, wh + WF_OM, om_b, omb, 0, 216, 576, 0);
        // DCN sampling -> [n][576][NPIX] fp16
        dcn_sample<<<(4*8*9*NPIX)/256, 256>>>(omb, sampt);
        // fused = relu(W_dcn @ sampled) : dense K=576 -> fp16 padded
        tgemm<128,1,1,1><<<dim3(72, 1, 4), 256, SMEM_GEMM_TOTAL>>>(
            sampt, 576L*NPIX, 0, wh + WF_DCN, dcn_b, fub, 128L*PPIX, 128, 576, 0);
        // cc = conv3x3(fused) + fused LSTM epilogue (writes h/c/fb directly)
        tgemm<128,0,0,4><<<dim3(72, 2, 4), 256, SMEM_LSTM_TOTAL>>>(
            fub, 128L*PPIX, 7, wh + WF_CC, conv_b, (void*)0, 0, 256, 1152, t);
    }

    // out[b][t] = conv3x3(concat(fwd,bwd)) over all 10 (t,b) lanes (M64)
    tgemm<64,0,0,2><<<dim3(72, 1, 10), 256, SMEM_GEMM_TOTAL>>>(
        fb, 128L*PPIX, 7, wh + WF_CAT, cat_b, d_out, 0, 64, 1152, 0);
}